// round 15
// baseline (speedup 1.0000x reference)
#include <cuda_runtime.h>
#include <cuda_fp16.h>
#include <cstdint>

#define DEPTH 4
#define B_    4096
#define H_    1024
#define K_    2048
#define N4H   4096

// ---------------- device scratch ----------------
__device__ __half g_A[DEPTH][B_][K_];    // [prev_out | s_h] fp16
__device__ __half g_W[DEPTH][K_][N4H];   // gate-interleaved: col 4j+g = orig g*1024+j
__device__ int    g_ticket;
__device__ int    g_ready[DEPTH][32];    // finished n-tiles per (layer, m-block)

// ---------------- helpers ----------------
__device__ __forceinline__ uint32_t smem_u32(const void* p) {
    uint32_t a;
    asm("{ .reg .u64 t; cvta.to.shared.u64 t, %1; cvt.u32.u64 %0, t; }" : "=r"(a) : "l"(p));
    return a;
}
__device__ __forceinline__ void cp16(uint32_t dst, const void* src) {
    asm volatile("cp.async.cg.shared.global [%0], [%1], 16;"
                 :: "r"(dst), "l"(__cvta_generic_to_global(src)));
}
__device__ __forceinline__ void ldsm4(uint32_t* r, uint32_t addr) {
    asm volatile("ldmatrix.sync.aligned.m8n8.x4.shared.b16 {%0,%1,%2,%3}, [%4];"
                 : "=r"(r[0]), "=r"(r[1]), "=r"(r[2]), "=r"(r[3]) : "r"(addr));
}
__device__ __forceinline__ void ldsm4t(uint32_t* r, uint32_t addr) {
    asm volatile("ldmatrix.sync.aligned.m8n8.x4.trans.shared.b16 {%0,%1,%2,%3}, [%4];"
                 : "=r"(r[0]), "=r"(r[1]), "=r"(r[2]), "=r"(r[3]) : "r"(addr));
}
__device__ __forceinline__ void mma16816(float* c, const uint32_t* a, const uint32_t* b) {
    asm volatile("mma.sync.aligned.m16n8k16.row.col.f32.f16.f16.f32 "
                 "{%0,%1,%2,%3}, {%4,%5,%6,%7}, {%8,%9}, {%0,%1,%2,%3};"
                 : "+f"(c[0]), "+f"(c[1]), "+f"(c[2]), "+f"(c[3])
                 : "r"(a[0]), "r"(a[1]), "r"(a[2]), "r"(a[3]), "r"(b[0]), "r"(b[1]));
}
__device__ __forceinline__ float sigm(float x) { return 1.0f / (1.0f + __expf(-x)); }

__device__ __forceinline__ void wait_ge(const int* cp, int thr) {
    int v;
    for (;;) {
        asm volatile("ld.global.acquire.gpu.b32 %0, [%1];" : "=r"(v) : "l"(cp) : "memory");
        if (v >= thr) break;
        __nanosleep(128);
    }
}
__device__ __forceinline__ void stcs4(float* p, float4 v) {
    asm volatile("st.global.cs.v4.f32 [%0], {%1,%2,%3,%4};"
                 :: "l"(__cvta_generic_to_global(p)), "f"(v.x), "f"(v.y), "f"(v.z), "f"(v.w)
                 : "memory");
}

// ---------------- merged prologue v2: MLP-batched ----------------
// blocks [0,4096): W gate-interleave, 2 j-quad units/thread (8 float4 loads in flight)
// blocks [4096,4608): x pack, 8 float4 units/thread batched
// blocks [4608,6656): s_h pack, 8 float4 units/thread batched
#define PREP_WBLK 4096
#define PREP_XBLK 512
#define PREP_SBLK 2048
#define PREP_GRID (PREP_WBLK + PREP_XBLK + PREP_SBLK)

__global__ void __launch_bounds__(256)
prep(const float* __restrict__ W, const float* __restrict__ x,
     const float* __restrict__ sh) {
    const int b = blockIdx.x;
    const int tid = threadIdx.x;
    if (b == 0) {
        if (tid == 0) g_ticket = 0;
        if (tid < DEPTH * 32) ((int*)g_ready)[tid] = 0;
    }
    if (b < PREP_WBLK) {
        // unit = (l,k,j4): 4 consecutive j columns. total = 4*2048*256 = 2M units.
        // 512 units/block, 2/thread. Load all 8 float4 first (MLP=8), then store.
        float4 vi[2], vf[2], vo[2], vg[2];
        size_t uu[2];
        #pragma unroll
        for (int u = 0; u < 2; ++u) {
            size_t i = (size_t)b * 512 + u * 256 + tid;
            uu[u] = i;
            size_t l = i >> 19;                        // / (2048*256)
            size_t rem = i & ((1u << 19) - 1);
            size_t k = rem >> 8, j4 = (rem & 255) << 2;
            const float* s = W + (l * K_ + k) * N4H + j4;
            vi[u] = *(const float4*)(s);
            vf[u] = *(const float4*)(s + 1024);
            vo[u] = *(const float4*)(s + 2048);
            vg[u] = *(const float4*)(s + 3072);
        }
        #pragma unroll
        for (int u = 0; u < 2; ++u) {
            size_t i = uu[u];
            size_t l = i >> 19;
            size_t rem = i & ((1u << 19) - 1);
            size_t k = rem >> 8, j4 = (rem & 255) << 2;
            __half2 h[8];
            h[0] = __floats2half2_rn(vi[u].x, vf[u].x);
            h[1] = __floats2half2_rn(vo[u].x, vg[u].x);
            h[2] = __floats2half2_rn(vi[u].y, vf[u].y);
            h[3] = __floats2half2_rn(vo[u].y, vg[u].y);
            h[4] = __floats2half2_rn(vi[u].z, vf[u].z);
            h[5] = __floats2half2_rn(vo[u].z, vg[u].z);
            h[6] = __floats2half2_rn(vi[u].w, vf[u].w);
            h[7] = __floats2half2_rn(vo[u].w, vg[u].w);
            uint4* dst = (uint4*)&g_W[l][k][4 * j4];    // 32B contiguous, 32B-aligned
            dst[0] = ((uint4*)h)[0];
            dst[1] = ((uint4*)h)[1];
        }
    } else if (b < PREP_WBLK + PREP_XBLK) {
        // 1M float4 units; 2048/block, 8/thread, batched
        float4 v[8];
        #pragma unroll
        for (int it = 0; it < 8; ++it) {
            size_t i = (size_t)(b - PREP_WBLK) * 2048 + it * 256 + tid;
            v[it] = ((const float4*)x)[i];
        }
        #pragma unroll
        for (int it = 0; it < 8; ++it) {
            size_t i = (size_t)(b - PREP_WBLK) * 2048 + it * 256 + tid;
            size_t e = i * 4;
            size_t m = e >> 10, j = e & 1023;
            __half2 h[2];
            h[0] = __floats2half2_rn(v[it].x, v[it].y);
            h[1] = __floats2half2_rn(v[it].z, v[it].w);
            *(uint2*)&g_A[0][m][j] = *(uint2*)h;
        }
    } else {
        // 4M float4 units; 2048/block, 8/thread, batched
        float4 v[8];
        #pragma unroll
        for (int it = 0; it < 8; ++it) {
            size_t i = (size_t)(b - PREP_WBLK - PREP_XBLK) * 2048 + it * 256 + tid;
            v[it] = ((const float4*)sh)[i];
        }
        #pragma unroll
        for (int it = 0; it < 8; ++it) {
            size_t i = (size_t)(b - PREP_WBLK - PREP_XBLK) * 2048 + it * 256 + tid;
            size_t e = i * 4;
            size_t l = e / ((size_t)B_ * H_);
            size_t r = e % ((size_t)B_ * H_);
            size_t m = r >> 10, j = r & 1023;
            __half2 h[2];
            h[0] = __floats2half2_rn(v[it].x, v[it].y);
            h[1] = __floats2half2_rn(v[it].z, v[it].w);
            *(uint2*)&g_A[l][m][H_ + j] = *(uint2*)h;
        }
    }
}

// ---------------- tile config ----------------
#define BK      32
#define ASTRIDE 80
#define BSTRIDE 272
#define A_STG   (128 * ASTRIDE)    // 10240
#define B_STG   (BK * BSTRIDE)     // 8704
#define STG     (A_STG + B_STG)    // 18944
#define NSTAGE  5
#define CIN_STRIDE 144
#define CIN_BYTES  (128 * CIN_STRIDE)
#define SMEM_G  (NSTAGE * STG + CIN_BYTES)     // 113152
#define NTILES  (DEPTH * 32 * 32)              // 4096
#define GRID_P  296

// ---------------- persistent fused GEMM + LSTM (R14-proven, unchanged) ----------------
__global__ void __launch_bounds__(256, 2)
lstm_all(const float* __restrict__ bias_all, const float* __restrict__ sc_all,
         float* __restrict__ out_h, float* __restrict__ out_c,
         float* __restrict__ out_final) {
    extern __shared__ __align__(16) char smem[];
    __shared__ int s_t;
    const int tid = threadIdx.x;
    const int wid = tid >> 5, lane = tid & 31;
    const int wm = (wid >> 2) * 64, wn = (wid & 3) * 32;
    const uint32_t sbase = smem_u32(smem);
    const uint32_t scin  = sbase + NSTAGE * STG;

    const int ar = tid >> 1, ac = (tid & 1) * 2;
    const int br = tid >> 4, bc = tid & 15;

    uint32_t aoff[4], boff[2];
    #pragma unroll
    for (int mf = 0; mf < 4; ++mf)
        aoff[mf] = (wm + mf * 16 + (lane & 15)) * ASTRIDE + (lane >> 4) * 16;
    #pragma unroll
    for (int ns = 0; ns < 2; ++ns)
        boff[ns] = (lane & 15) * BSTRIDE + (wn + ns * 16 + (lane >> 4) * 8) * 2;

    for (;;) {
        if (tid == 0) s_t = atomicAdd(&g_ticket, 1);
        __syncthreads();
        const int t = s_t;
        if (t >= NTILES) return;
        const int layer = t >> 10;
        const int mb = (t >> 5) & 31;
        const int nb = t & 31;
        const int m0 = mb * 128, n0 = nb * 128;
        const int jbase = n0 >> 2;

        const float* bias = bias_all + (size_t)layer * N4H;
        const float* c_in = sc_all + (size_t)layer * B_ * H_;
        float* h_out = out_h + (size_t)layer * B_ * H_;
        float* c_out = out_c + (size_t)layer * B_ * H_;
        float* final_out = (layer == DEPTH - 1) ? out_final : nullptr;
        const __half* Ag = &g_A[layer][0][0];
        const __half* Wg = &g_W[layer][0][0];
        __half* a_next = (layer + 1 < DEPTH) ? &g_A[layer + 1][0][0] : nullptr;

        if (layer > 0) {
            if (tid == 0) wait_ge(&g_ready[layer - 1][mb], 32);
            __syncthreads();
        }

        auto load_stage = [&](int s, int k0) {
            uint32_t da = sbase + s * STG;
            uint32_t db = da + A_STG;
            cp16(da + ar * ASTRIDE + ac * 16,       Ag + (size_t)(m0 + ar) * K_ + k0 + ac * 8);
            cp16(da + ar * ASTRIDE + (ac + 1) * 16, Ag + (size_t)(m0 + ar) * K_ + k0 + (ac + 1) * 8);
            cp16(db + br * BSTRIDE + bc * 16,        Wg + (size_t)(k0 + br) * N4H + n0 + bc * 8);
            cp16(db + (br + 16) * BSTRIDE + bc * 16, Wg + (size_t)(k0 + br + 16) * N4H + n0 + bc * 8);
            asm volatile("cp.async.commit_group;" ::: "memory");
        };

        float acc[4][4][4];
        #pragma unroll
        for (int i = 0; i < 4; ++i)
            #pragma unroll
            for (int j = 0; j < 4; ++j)
                #pragma unroll
                for (int q2 = 0; q2 < 4; ++q2) acc[i][j][q2] = 0.f;

        // c_in prefetch (oldest group)
        #pragma unroll
        for (int it = 0; it < 4; ++it) {
            int idx = tid + 256 * it;
            int r = idx >> 3, ch = idx & 7;
            cp16(scin + r * CIN_STRIDE + ch * 16,
                 c_in + (size_t)(m0 + r) * H_ + jbase + ch * 4);
        }
        asm volatile("cp.async.commit_group;" ::: "memory");

        load_stage(0, 0);
        load_stage(1, BK);
        load_stage(2, 2 * BK);

        auto subiter = [&](int st, int pf_slot, int pf_k0, bool do_pf) {
            const uint32_t da = sbase + st * STG;
            const uint32_t db = da + A_STG;
            uint32_t af[4][4], bf[2][4];
            #pragma unroll
            for (int mf = 0; mf < 4; ++mf) ldsm4(af[mf], da + aoff[mf]);
            #pragma unroll
            for (int ns = 0; ns < 2; ++ns) ldsm4t(bf[ns], db + boff[ns]);
            if (do_pf) load_stage(pf_slot, pf_k0);
            #pragma unroll
            for (int mf = 0; mf < 4; ++mf)
                #pragma unroll
                for (int nf = 0; nf < 4; ++nf)
                    mma16816(acc[mf][nf], af[mf], &bf[nf >> 1][(nf & 1) * 2]);
            #pragma unroll
            for (int mf = 0; mf < 4; ++mf) ldsm4(af[mf], da + aoff[mf] + 32);
            #pragma unroll
            for (int ns = 0; ns < 2; ++ns) ldsm4t(bf[ns], db + boff[ns] + 16 * BSTRIDE);
            #pragma unroll
            for (int mf = 0; mf < 4; ++mf)
                #pragma unroll
                for (int nf = 0; nf < 4; ++nf)
                    mma16816(acc[mf][nf], af[mf], &bf[nf >> 1][(nf & 1) * 2]);
        };

        const int NIT = K_ / BK;  // 64
        #pragma unroll 1
        for (int kt = 0; kt < NIT; kt += 2) {
            if (kt + 2 < NIT) asm volatile("cp.async.wait_group 1;" ::: "memory");
            else              asm volatile("cp.async.wait_group 0;" ::: "memory");
            __syncthreads();
            subiter(kt % NSTAGE,       (kt + 3) % NSTAGE, (kt + 3) * BK, kt + 3 < NIT);
            subiter((kt + 1) % NSTAGE, (kt + 4) % NSTAGE, (kt + 4) * BK, kt + 4 < NIT);
        }
        __syncthreads();

        // ---- LSTM epilogue (staging in slot-3/4 region; mapping verified) ----
        float* sh_h = (float*)(smem + 3 * STG);          // [128][33]
        float* sh_c = sh_h + 128 * 33;                   // [128][33]
        const float* sh_cin = (const float*)(smem + NSTAGE * STG);

        const int q = lane & 3;
        const bool has_if = (q & 1) == 0;
        const int rloc = wm + (lane >> 2);

        float bi[4], bfs[4], bo[4], bg[4];
        int jloc[4];
        #pragma unroll
        for (int nf = 0; nf < 4; ++nf) {
            int jl = (wn >> 2) + nf * 2 + (q >> 1);
            jloc[nf] = jl;
            int j = jbase + jl;
            bi[nf]  = bias[j];
            bfs[nf] = bias[1024 + j];
            bo[nf]  = bias[2048 + j];
            bg[nf]  = bias[3072 + j];
        }

        #pragma unroll
        for (int mf = 0; mf < 4; ++mf) {
            #pragma unroll
            for (int nf = 0; nf < 4; ++nf) {
                float v0 = acc[mf][nf][0], v1 = acc[mf][nf][1];
                float v2 = acc[mf][nf][2], v3 = acc[mf][nf][3];
                float p0 = __shfl_xor_sync(0xffffffffu, v0, 1);
                float p1 = __shfl_xor_sync(0xffffffffu, v1, 1);
                float p2 = __shfl_xor_sync(0xffffffffu, v2, 1);
                float p3 = __shfl_xor_sync(0xffffffffu, v3, 1);
                float zi, zf, zo, zg;
                int ml;
                if (has_if) { zi = v0; zf = v1; zo = p0; zg = p1; ml = rloc + mf * 16; }
                else        { zi = p2; zf = p3; zo = v2; zg = v3; ml = rloc + mf * 16 + 8; }
                const int jl = jloc[nf];
                float ig = sigm(zi + bi[nf]);
                float fg = sigm(zf + bfs[nf]);
                float og = sigm(zo + bo[nf]);
                float gg = tanhf(zg + bg[nf]);
                float cn = sh_cin[ml * 36 + jl] * fg + gg * ig;
                float hn = tanhf(cn) * og;
                sh_h[ml * 33 + jl] = hn;
                sh_c[ml * 33 + jl] = cn;
            }
        }
        __syncthreads();

        // ---- vectorized output pass ----
        #pragma unroll
        for (int it = 0; it < 4; ++it) {
            int idx = tid + 256 * it;            // 0..1023
            int r = idx >> 3, c4 = (idx & 7) * 4;
            float4 hv = make_float4(sh_h[r * 33 + c4],     sh_h[r * 33 + c4 + 1],
                                    sh_h[r * 33 + c4 + 2], sh_h[r * 33 + c4 + 3]);
            float4 cv = make_float4(sh_c[r * 33 + c4],     sh_c[r * 33 + c4 + 1],
                                    sh_c[r * 33 + c4 + 2], sh_c[r * 33 + c4 + 3]);
            const size_t off = (size_t)(m0 + r) * H_ + jbase + c4;
            stcs4(&h_out[off], hv);
            stcs4(&c_out[off], cv);
            if (final_out) stcs4(&final_out[off], hv);
            if (a_next) {
                __half2 pk[2];
                pk[0] = __floats2half2_rn(hv.x, hv.y);
                pk[1] = __floats2half2_rn(hv.z, hv.w);
                *(uint2*)&a_next[(size_t)(m0 + r) * K_ + jbase + c4] = *(uint2*)pk;
            }
        }
        __syncthreads();
        if (tid == 0)
            asm volatile("red.release.gpu.global.add.s32 [%0], 1;"
                         :: "l"(__cvta_generic_to_global(&g_ready[layer][mb])) : "memory");
    }
}

// ---------------- launch ----------------
extern "C" void kernel_launch(void* const* d_in, const int* in_sizes, int n_in,
                              void* d_out, int out_size) {
    const float* x  = (const float*)d_in[0];
    const float* sh = (const float*)d_in[1];
    const float* sc = (const float*)d_in[2];
    const float* W  = (const float*)d_in[3];
    const float* b  = (const float*)d_in[4];
    float* out = (float*)d_out;

    const size_t BH = (size_t)B_ * H_;
    float* out_final = out;
    float* out_h     = out + BH;
    float* out_c     = out + BH + DEPTH * BH;

    cudaFuncSetAttribute(lstm_all, cudaFuncAttributeMaxDynamicSharedMemorySize, SMEM_G);

    prep<<<PREP_GRID, 256>>>(W, x, sh);
    lstm_all<<<GRID_P, 256, SMEM_G>>>(b, sc, out_h, out_c, out_final);
}

// round 16
// speedup vs baseline: 1.0800x; 1.0800x over previous
#include <cuda_runtime.h>
#include <cuda_fp16.h>
#include <cstdint>

#define DEPTH 4
#define B_    4096
#define H_    1024
#define K_    2048
#define N4H   4096

// ---------------- device scratch ----------------
__device__ __half g_A[DEPTH][B_][K_];    // [prev_out | s_h] fp16
__device__ __half g_W[DEPTH][K_][N4H];   // gate-interleaved: col 4j+g = orig g*1024+j
__device__ int    g_ticket;
__device__ int    g_ready[DEPTH][32];    // finished n-tiles per (layer, m-block)

// ---------------- helpers ----------------
__device__ __forceinline__ uint32_t smem_u32(const void* p) {
    uint32_t a;
    asm("{ .reg .u64 t; cvta.to.shared.u64 t, %1; cvt.u32.u64 %0, t; }" : "=r"(a) : "l"(p));
    return a;
}
__device__ __forceinline__ void cp16(uint32_t dst, const void* src) {
    asm volatile("cp.async.cg.shared.global [%0], [%1], 16;"
                 :: "r"(dst), "l"(__cvta_generic_to_global(src)));
}
__device__ __forceinline__ void ldsm4(uint32_t* r, uint32_t addr) {
    asm volatile("ldmatrix.sync.aligned.m8n8.x4.shared.b16 {%0,%1,%2,%3}, [%4];"
                 : "=r"(r[0]), "=r"(r[1]), "=r"(r[2]), "=r"(r[3]) : "r"(addr));
}
__device__ __forceinline__ void ldsm4t(uint32_t* r, uint32_t addr) {
    asm volatile("ldmatrix.sync.aligned.m8n8.x4.trans.shared.b16 {%0,%1,%2,%3}, [%4];"
                 : "=r"(r[0]), "=r"(r[1]), "=r"(r[2]), "=r"(r[3]) : "r"(addr));
}
__device__ __forceinline__ void mma16816(float* c, const uint32_t* a, const uint32_t* b) {
    asm volatile("mma.sync.aligned.m16n8k16.row.col.f32.f16.f16.f32 "
                 "{%0,%1,%2,%3}, {%4,%5,%6,%7}, {%8,%9}, {%0,%1,%2,%3};"
                 : "+f"(c[0]), "+f"(c[1]), "+f"(c[2]), "+f"(c[3])
                 : "r"(a[0]), "r"(a[1]), "r"(a[2]), "r"(a[3]), "r"(b[0]), "r"(b[1]));
}
__device__ __forceinline__ float sigm(float x) { return 1.0f / (1.0f + __expf(-x)); }

__device__ __forceinline__ void wait_ge(const int* cp, int thr) {
    int v;
    for (;;) {
        asm volatile("ld.global.acquire.gpu.b32 %0, [%1];" : "=r"(v) : "l"(cp) : "memory");
        if (v >= thr) break;
        __nanosleep(128);
    }
}
__device__ __forceinline__ void stcs4(float* p, float4 v) {
    asm volatile("st.global.cs.v4.f32 [%0], {%1,%2,%3,%4};"
                 :: "l"(__cvta_generic_to_global(p)), "f"(v.x), "f"(v.y), "f"(v.z), "f"(v.w)
                 : "memory");
}

// ---- mbarrier primitives (baseline sm_80+ PTX; NOT tcgen05-gated) ----
#define MBAR_INIT(mb, n) \
    asm volatile("mbarrier.init.shared.b64 [%0], %1;" \
                 :: "r"((uint32_t)(mb)), "r"((uint32_t)(n)) : "memory")
#define MBAR_ARRIVE(mb) \
    asm volatile("mbarrier.arrive.shared.b64 _, [%0];" :: "r"((uint32_t)(mb)) : "memory")
#define CPASYNC_MBAR_ARRIVE(mb) \
    asm volatile("cp.async.mbarrier.arrive.noinc.shared.b64 [%0];" \
                 :: "r"((uint32_t)(mb)) : "memory")
#define MBAR_WAIT(mb_, par_) do {                                                        \
    uint32_t _mb = (uint32_t)(mb_);  uint32_t _pr = (uint32_t)(par_);  uint32_t _dn;     \
    asm volatile("{\n\t.reg .pred p;\n\t"                                                \
        "mbarrier.try_wait.parity.acquire.cta.shared::cta.b64 p, [%1], %2;\n\t"          \
        "selp.b32 %0, 1, 0, p;\n\t}" : "=r"(_dn) : "r"(_mb), "r"(_pr) : "memory");       \
    if (!_dn) {                                                                          \
        asm volatile("{\n\t.reg .pred P1;\n\t"                                           \
            "WL_%=:\n\t"                                                                 \
            "mbarrier.try_wait.parity.acquire.cta.shared::cta.b64 P1, [%0], %1, 0x989680;\n\t" \
            "@P1 bra.uni WD_%=;\n\tbra.uni WL_%=;\n\tWD_%=:\n\t}"                        \
            :: "r"(_mb), "r"(_pr) : "memory");                                           \
    }                                                                                    \
} while (0)

// ---------------- merged prologue (R15; at HBM floor ~40us) ----------------
#define PREP_WBLK 4096
#define PREP_XBLK 512
#define PREP_SBLK 2048
#define PREP_GRID (PREP_WBLK + PREP_XBLK + PREP_SBLK)

__global__ void __launch_bounds__(256)
prep(const float* __restrict__ W, const float* __restrict__ x,
     const float* __restrict__ sh) {
    const int b = blockIdx.x;
    const int tid = threadIdx.x;
    if (b == 0) {
        if (tid == 0) g_ticket = 0;
        if (tid < DEPTH * 32) ((int*)g_ready)[tid] = 0;
    }
    if (b < PREP_WBLK) {
        float4 vi[2], vf[2], vo[2], vg[2];
        size_t uu[2];
        #pragma unroll
        for (int u = 0; u < 2; ++u) {
            size_t i = (size_t)b * 512 + u * 256 + tid;
            uu[u] = i;
            size_t l = i >> 19;
            size_t rem = i & ((1u << 19) - 1);
            size_t k = rem >> 8, j4 = (rem & 255) << 2;
            const float* s = W + (l * K_ + k) * N4H + j4;
            vi[u] = *(const float4*)(s);
            vf[u] = *(const float4*)(s + 1024);
            vo[u] = *(const float4*)(s + 2048);
            vg[u] = *(const float4*)(s + 3072);
        }
        #pragma unroll
        for (int u = 0; u < 2; ++u) {
            size_t i = uu[u];
            size_t l = i >> 19;
            size_t rem = i & ((1u << 19) - 1);
            size_t k = rem >> 8, j4 = (rem & 255) << 2;
            __half2 h[8];
            h[0] = __floats2half2_rn(vi[u].x, vf[u].x);
            h[1] = __floats2half2_rn(vo[u].x, vg[u].x);
            h[2] = __floats2half2_rn(vi[u].y, vf[u].y);
            h[3] = __floats2half2_rn(vo[u].y, vg[u].y);
            h[4] = __floats2half2_rn(vi[u].z, vf[u].z);
            h[5] = __floats2half2_rn(vo[u].z, vg[u].z);
            h[6] = __floats2half2_rn(vi[u].w, vf[u].w);
            h[7] = __floats2half2_rn(vo[u].w, vg[u].w);
            uint4* dst = (uint4*)&g_W[l][k][4 * j4];
            dst[0] = ((uint4*)h)[0];
            dst[1] = ((uint4*)h)[1];
        }
    } else if (b < PREP_WBLK + PREP_XBLK) {
        float4 v[8];
        #pragma unroll
        for (int it = 0; it < 8; ++it) {
            size_t i = (size_t)(b - PREP_WBLK) * 2048 + it * 256 + tid;
            v[it] = ((const float4*)x)[i];
        }
        #pragma unroll
        for (int it = 0; it < 8; ++it) {
            size_t i = (size_t)(b - PREP_WBLK) * 2048 + it * 256 + tid;
            size_t e = i * 4;
            size_t m = e >> 10, j = e & 1023;
            __half2 h[2];
            h[0] = __floats2half2_rn(v[it].x, v[it].y);
            h[1] = __floats2half2_rn(v[it].z, v[it].w);
            *(uint2*)&g_A[0][m][j] = *(uint2*)h;
        }
    } else {
        float4 v[8];
        #pragma unroll
        for (int it = 0; it < 8; ++it) {
            size_t i = (size_t)(b - PREP_WBLK - PREP_XBLK) * 2048 + it * 256 + tid;
            v[it] = ((const float4*)sh)[i];
        }
        #pragma unroll
        for (int it = 0; it < 8; ++it) {
            size_t i = (size_t)(b - PREP_WBLK - PREP_XBLK) * 2048 + it * 256 + tid;
            size_t e = i * 4;
            size_t l = e / ((size_t)B_ * H_);
            size_t r = e % ((size_t)B_ * H_);
            size_t m = r >> 10, j = r & 1023;
            __half2 h[2];
            h[0] = __floats2half2_rn(v[it].x, v[it].y);
            h[1] = __floats2half2_rn(v[it].z, v[it].w);
            *(uint2*)&g_A[l][m][H_ + j] = *(uint2*)h;
        }
    }
}

// ---------------- tile config ----------------
#define BK      32
#define ASTRIDE 80
#define BSTRIDE 272
#define A_STG   (128 * ASTRIDE)    // 10240
#define B_STG   (BK * BSTRIDE)     // 8704
#define STG     (A_STG + B_STG)    // 18944
#define NSTAGE  5
#define CIN_STRIDE 144
#define CIN_BYTES  (128 * CIN_STRIDE)
#define SMEM_G  (NSTAGE * STG + CIN_BYTES)     // 113152
#define NTILES  (DEPTH * 32 * 32)              // 4096
#define GRID_P  296
#define NIT     (K_ / BK)                      // 64

// ---------------- persistent fused GEMM + LSTM, mbarrier pipeline ----------------
__global__ void __launch_bounds__(256, 2)
lstm_all(const float* __restrict__ bias_all, const float* __restrict__ sc_all,
         float* __restrict__ out_h, float* __restrict__ out_c,
         float* __restrict__ out_final) {
    extern __shared__ __align__(16) char smem[];
    __shared__ int s_t;
    __shared__ __align__(16) uint64_t s_mb[2 * NSTAGE];   // full[0..4], empty[0..4]
    const int tid = threadIdx.x;
    const int wid = tid >> 5, lane = tid & 31;
    const int wm = (wid >> 2) * 64, wn = (wid & 3) * 32;
    const uint32_t sbase = smem_u32(smem);
    const uint32_t scin  = sbase + NSTAGE * STG;
    const uint32_t mbF   = smem_u32(&s_mb[0]);
    const uint32_t mbE   = smem_u32(&s_mb[NSTAGE]);

    const int ar = tid >> 1, ac = (tid & 1) * 2;
    const int br = tid >> 4, bc = tid & 15;

    uint32_t aoff[4], boff[2];
    #pragma unroll
    for (int mf = 0; mf < 4; ++mf)
        aoff[mf] = (wm + mf * 16 + (lane & 15)) * ASTRIDE + (lane >> 4) * 16;
    #pragma unroll
    for (int ns = 0; ns < 2; ++ns)
        boff[ns] = (lane & 15) * BSTRIDE + (wn + ns * 16 + (lane >> 4) * 8) * 2;

    for (;;) {
        if (tid == 0) s_t = atomicAdd(&g_ticket, 1);
        __syncthreads();
        const int t = s_t;
        if (t >= NTILES) return;
        const int layer = t >> 10;
        const int mb = (t >> 5) & 31;
        const int nb = t & 31;
        const int m0 = mb * 128, n0 = nb * 128;
        const int jbase = n0 >> 2;

        const float* bias = bias_all + (size_t)layer * N4H;
        const float* c_in = sc_all + (size_t)layer * B_ * H_;
        float* h_out = out_h + (size_t)layer * B_ * H_;
        float* c_out = out_c + (size_t)layer * B_ * H_;
        float* final_out = (layer == DEPTH - 1) ? out_final : nullptr;
        const __half* Ag = &g_A[layer][0][0];
        const __half* Wg = &g_W[layer][0][0];
        __half* a_next = (layer + 1 < DEPTH) ? &g_A[layer + 1][0][0] : nullptr;

        // per-tile barrier re-init (all prior arrivals retired: balanced 13/13 cycles)
        if (tid == 0) {
            #pragma unroll
            for (int s = 0; s < NSTAGE; ++s) {
                MBAR_INIT(mbF + s * 8, 256);
                MBAR_INIT(mbE + s * 8, 256);
            }
            if (layer > 0) wait_ge(&g_ready[layer - 1][mb], 32);
        }
        __syncthreads();

        // c_in: own commit group (only committed group; stage loads are uncommitted)
        #pragma unroll
        for (int it = 0; it < 4; ++it) {
            int idx = tid + 256 * it;
            int r = idx >> 3, ch = idx & 7;
            cp16(scin + r * CIN_STRIDE + ch * 16,
                 c_in + (size_t)(m0 + r) * H_ + jbase + ch * 4);
        }
        asm volatile("cp.async.commit_group;" ::: "memory");

        auto load_stage = [&](int s, int k0) {
            uint32_t da = sbase + s * STG;
            uint32_t db = da + A_STG;
            cp16(da + ar * ASTRIDE + ac * 16,       Ag + (size_t)(m0 + ar) * K_ + k0 + ac * 8);
            cp16(da + ar * ASTRIDE + (ac + 1) * 16, Ag + (size_t)(m0 + ar) * K_ + k0 + (ac + 1) * 8);
            cp16(db + br * BSTRIDE + bc * 16,        Wg + (size_t)(k0 + br) * N4H + n0 + bc * 8);
            cp16(db + (br + 16) * BSTRIDE + bc * 16, Wg + (size_t)(k0 + br + 16) * N4H + n0 + bc * 8);
            CPASYNC_MBAR_ARRIVE(mbF + s * 8);
        };

        // prologue: fill all 5 stages (fresh barriers, no empty-wait)
        #pragma unroll
        for (int s = 0; s < NSTAGE; ++s) load_stage(s, s * BK);

        float acc[4][4][4];
        #pragma unroll
        for (int i = 0; i < 4; ++i)
            #pragma unroll
            for (int j = 0; j < 4; ++j)
                #pragma unroll
                for (int q2 = 0; q2 < 4; ++q2) acc[i][j][q2] = 0.f;

        // mainloop: slot = kt%5, parity ph = (kt/5)&1, flips per 5-iter macro block
        int ph = 0;
        #pragma unroll 1
        for (int kt = 0; kt < NIT; ++kt) {
            const int slot = kt % NSTAGE;
            const uint32_t da = sbase + slot * STG;
            const uint32_t db = da + A_STG;

            MBAR_WAIT(mbF + slot * 8, ph);

            uint32_t af[4][4], bf[2][4];
            #pragma unroll
            for (int mf = 0; mf < 4; ++mf) ldsm4(af[mf], da + aoff[mf]);
            #pragma unroll
            for (int ns = 0; ns < 2; ++ns) ldsm4t(bf[ns], db + boff[ns]);
            #pragma unroll
            for (int mf = 0; mf < 4; ++mf)
                #pragma unroll
                for (int nf = 0; nf < 4; ++nf)
                    mma16816(acc[mf][nf], af[mf], &bf[nf >> 1][(nf & 1) * 2]);
            #pragma unroll
            for (int mf = 0; mf < 4; ++mf) ldsm4(af[mf], da + aoff[mf] + 32);
            #pragma unroll
            for (int ns = 0; ns < 2; ++ns) ldsm4t(bf[ns], db + boff[ns] + 16 * BSTRIDE);
            MBAR_ARRIVE(mbE + slot * 8);     // this thread done reading slot (use kt/5)
            #pragma unroll
            for (int mf = 0; mf < 4; ++mf)
                #pragma unroll
                for (int nf = 0; nf < 4; ++nf)
                    mma16816(acc[mf][nf], af[mf], &bf[nf >> 1][(nf & 1) * 2]);

            if (kt + NSTAGE < NIT) {
                MBAR_WAIT(mbE + slot * 8, ph);      // all 256 done with use kt/5
                load_stage(slot, (kt + NSTAGE) * BK);
            }
            if (slot == NSTAGE - 1) ph ^= 1;
        }

        asm volatile("cp.async.wait_group 0;" ::: "memory");   // c_in group
        __syncthreads();   // all ldsm of slots 3/4 done before staging reuse

        // ---- LSTM epilogue (staging in slot-3/4 region; mapping verified) ----
        float* sh_h = (float*)(smem + 3 * STG);          // [128][33]
        float* sh_c = sh_h + 128 * 33;                   // [128][33]
        const float* sh_cin = (const float*)(smem + NSTAGE * STG);

        const int q = lane & 3;
        const bool has_if = (q & 1) == 0;
        const int rloc = wm + (lane >> 2);

        float bi[4], bfs[4], bo[4], bg[4];
        int jloc[4];
        #pragma unroll
        for (int nf = 0; nf < 4; ++nf) {
            int jl = (wn >> 2) + nf * 2 + (q >> 1);
            jloc[nf] = jl;
            int j = jbase + jl;
            bi[nf]  = bias[j];
            bfs[nf] = bias[1024 + j];
            bo[nf]  = bias[2048 + j];
            bg[nf]  = bias[3072 + j];
        }

        #pragma unroll
        for (int mf = 0; mf < 4; ++mf) {
            #pragma unroll
            for (int nf = 0; nf < 4; ++nf) {
                float v0 = acc[mf][nf][0], v1 = acc[mf][nf][1];
                float v2 = acc[mf][nf][2], v3 = acc[mf][nf][3];
                float p0 = __shfl_xor_sync(0xffffffffu, v0, 1);
                float p1 = __shfl_xor_sync(0xffffffffu, v1, 1);
                float p2 = __shfl_xor_sync(0xffffffffu, v2, 1);
                float p3 = __shfl_xor_sync(0xffffffffu, v3, 1);
                float zi, zf, zo, zg;
                int ml;
                if (has_if) { zi = v0; zf = v1; zo = p0; zg = p1; ml = rloc + mf * 16; }
                else        { zi = p2; zf = p3; zo = v2; zg = v3; ml = rloc + mf * 16 + 8; }
                const int jl = jloc[nf];
                float ig = sigm(zi + bi[nf]);
                float fg = sigm(zf + bfs[nf]);
                float og = sigm(zo + bo[nf]);
                float gg = tanhf(zg + bg[nf]);
                float cn = sh_cin[ml * 36 + jl] * fg + gg * ig;
                float hn = tanhf(cn) * og;
                sh_h[ml * 33 + jl] = hn;
                sh_c[ml * 33 + jl] = cn;
            }
        }
        __syncthreads();

        // ---- vectorized output pass ----
        #pragma unroll
        for (int it = 0; it < 4; ++it) {
            int idx = tid + 256 * it;            // 0..1023
            int r = idx >> 3, c4 = (idx & 7) * 4;
            float4 hv = make_float4(sh_h[r * 33 + c4],     sh_h[r * 33 + c4 + 1],
                                    sh_h[r * 33 + c4 + 2], sh_h[r * 33 + c4 + 3]);
            float4 cv = make_float4(sh_c[r * 33 + c4],     sh_c[r * 33 + c4 + 1],
                                    sh_c[r * 33 + c4 + 2], sh_c[r * 33 + c4 + 3]);
            const size_t off = (size_t)(m0 + r) * H_ + jbase + c4;
            stcs4(&h_out[off], hv);
            stcs4(&c_out[off], cv);
            if (final_out) stcs4(&final_out[off], hv);
            if (a_next) {
                __half2 pk[2];
                pk[0] = __floats2half2_rn(hv.x, hv.y);
                pk[1] = __floats2half2_rn(hv.z, hv.w);
                *(uint2*)&a_next[(size_t)(m0 + r) * K_ + jbase + c4] = *(uint2*)pk;
            }
        }
        __syncthreads();
        if (tid == 0)
            asm volatile("red.release.gpu.global.add.s32 [%0], 1;"
                         :: "l"(__cvta_generic_to_global(&g_ready[layer][mb])) : "memory");
    }
}

// ---------------- launch ----------------
extern "C" void kernel_launch(void* const* d_in, const int* in_sizes, int n_in,
                              void* d_out, int out_size) {
    const float* x  = (const float*)d_in[0];
    const float* sh = (const float*)d_in[1];
    const float* sc = (const float*)d_in[2];
    const float* W  = (const float*)d_in[3];
    const float* b  = (const float*)d_in[4];
    float* out = (float*)d_out;

    const size_t BH = (size_t)B_ * H_;
    float* out_final = out;
    float* out_h     = out + BH;
    float* out_c     = out + BH + DEPTH * BH;

    cudaFuncSetAttribute(lstm_all, cudaFuncAttributeMaxDynamicSharedMemorySize, SMEM_G);

    prep<<<PREP_GRID, 256>>>(W, x, sh);
    lstm_all<<<GRID_P, 256, SMEM_G>>>(b, sc, out_h, out_c, out_final);
}

// round 17
// speedup vs baseline: 1.1572x; 1.0715x over previous
#include <cuda_runtime.h>
#include <cuda_fp16.h>
#include <cstdint>

#define DEPTH 4
#define B_    4096
#define H_    1024
#define K_    2048
#define N4H   4096

// ---------------- device scratch ----------------
__device__ __half g_A[DEPTH][B_][K_];    // [prev_out | s_h] fp16
__device__ __half g_W[DEPTH][K_][N4H];   // gate-interleaved: col 4j+g = orig g*1024+j
__device__ int    g_ticket;
__device__ int    g_ready[DEPTH][32];    // finished n-tiles per (layer, m-block)

// ---------------- helpers ----------------
__device__ __forceinline__ uint32_t smem_u32(const void* p) {
    uint32_t a;
    asm("{ .reg .u64 t; cvta.to.shared.u64 t, %1; cvt.u32.u64 %0, t; }" : "=r"(a) : "l"(p));
    return a;
}
__device__ __forceinline__ void cp16(uint32_t dst, const void* src) {
    asm volatile("cp.async.cg.shared.global [%0], [%1], 16;"
                 :: "r"(dst), "l"(__cvta_generic_to_global(src)));
}
__device__ __forceinline__ void ldsm4(uint32_t* r, uint32_t addr) {
    asm volatile("ldmatrix.sync.aligned.m8n8.x4.shared.b16 {%0,%1,%2,%3}, [%4];"
                 : "=r"(r[0]), "=r"(r[1]), "=r"(r[2]), "=r"(r[3]) : "r"(addr));
}
__device__ __forceinline__ void ldsm4t(uint32_t* r, uint32_t addr) {
    asm volatile("ldmatrix.sync.aligned.m8n8.x4.trans.shared.b16 {%0,%1,%2,%3}, [%4];"
                 : "=r"(r[0]), "=r"(r[1]), "=r"(r[2]), "=r"(r[3]) : "r"(addr));
}
__device__ __forceinline__ void mma16816(float* c, const uint32_t* a, const uint32_t* b) {
    asm volatile("mma.sync.aligned.m16n8k16.row.col.f32.f16.f16.f32 "
                 "{%0,%1,%2,%3}, {%4,%5,%6,%7}, {%8,%9}, {%0,%1,%2,%3};"
                 : "+f"(c[0]), "+f"(c[1]), "+f"(c[2]), "+f"(c[3])
                 : "r"(a[0]), "r"(a[1]), "r"(a[2]), "r"(a[3]), "r"(b[0]), "r"(b[1]));
}
__device__ __forceinline__ float sigm(float x) { return 1.0f / (1.0f + __expf(-x)); }

__device__ __forceinline__ void wait_ge(const int* cp, int thr) {
    int v;
    for (;;) {
        asm volatile("ld.global.acquire.gpu.b32 %0, [%1];" : "=r"(v) : "l"(cp) : "memory");
        if (v >= thr) break;
        __nanosleep(128);
    }
}
__device__ __forceinline__ void stcs4(float* p, float4 v) {
    asm volatile("st.global.cs.v4.f32 [%0], {%1,%2,%3,%4};"
                 :: "l"(__cvta_generic_to_global(p)), "f"(v.x), "f"(v.y), "f"(v.z), "f"(v.w)
                 : "memory");
}

// ---- mbarrier primitives (baseline sm_80+ PTX) ----
#define MBAR_INIT(mb, n) \
    asm volatile("mbarrier.init.shared.b64 [%0], %1;" \
                 :: "r"((uint32_t)(mb)), "r"((uint32_t)(n)) : "memory")
#define MBAR_ARRIVE(mb) \
    asm volatile("mbarrier.arrive.shared.b64 _, [%0];" :: "r"((uint32_t)(mb)) : "memory")
#define CPASYNC_MBAR_ARRIVE(mb) \
    asm volatile("cp.async.mbarrier.arrive.noinc.shared.b64 [%0];" \
                 :: "r"((uint32_t)(mb)) : "memory")
#define MBAR_WAIT(mb_, par_) do {                                                        \
    uint32_t _mb = (uint32_t)(mb_);  uint32_t _pr = (uint32_t)(par_);  uint32_t _dn;     \
    asm volatile("{\n\t.reg .pred p;\n\t"                                                \
        "mbarrier.try_wait.parity.acquire.cta.shared::cta.b64 p, [%1], %2;\n\t"          \
        "selp.b32 %0, 1, 0, p;\n\t}" : "=r"(_dn) : "r"(_mb), "r"(_pr) : "memory");       \
    if (!_dn) {                                                                          \
        asm volatile("{\n\t.reg .pred P1;\n\t"                                           \
            "WL_%=:\n\t"                                                                 \
            "mbarrier.try_wait.parity.acquire.cta.shared::cta.b64 P1, [%0], %1, 0x989680;\n\t" \
            "@P1 bra.uni WD_%=;\n\tbra.uni WL_%=;\n\tWD_%=:\n\t}"                        \
            :: "r"(_mb), "r"(_pr) : "memory");                                           \
    }                                                                                    \
} while (0)

// ---------------- merged prologue (at HBM floor ~40us) ----------------
#define PREP_WBLK 4096
#define PREP_XBLK 512
#define PREP_SBLK 2048
#define PREP_GRID (PREP_WBLK + PREP_XBLK + PREP_SBLK)

__global__ void __launch_bounds__(256)
prep(const float* __restrict__ W, const float* __restrict__ x,
     const float* __restrict__ sh) {
    const int b = blockIdx.x;
    const int tid = threadIdx.x;
    if (b == 0) {
        if (tid == 0) g_ticket = 0;
        if (tid < DEPTH * 32) ((int*)g_ready)[tid] = 0;
    }
    if (b < PREP_WBLK) {
        float4 vi[2], vf[2], vo[2], vg[2];
        size_t uu[2];
        #pragma unroll
        for (int u = 0; u < 2; ++u) {
            size_t i = (size_t)b * 512 + u * 256 + tid;
            uu[u] = i;
            size_t l = i >> 19;
            size_t rem = i & ((1u << 19) - 1);
            size_t k = rem >> 8, j4 = (rem & 255) << 2;
            const float* s = W + (l * K_ + k) * N4H + j4;
            vi[u] = *(const float4*)(s);
            vf[u] = *(const float4*)(s + 1024);
            vo[u] = *(const float4*)(s + 2048);
            vg[u] = *(const float4*)(s + 3072);
        }
        #pragma unroll
        for (int u = 0; u < 2; ++u) {
            size_t i = uu[u];
            size_t l = i >> 19;
            size_t rem = i & ((1u << 19) - 1);
            size_t k = rem >> 8, j4 = (rem & 255) << 2;
            __half2 h[8];
            h[0] = __floats2half2_rn(vi[u].x, vf[u].x);
            h[1] = __floats2half2_rn(vo[u].x, vg[u].x);
            h[2] = __floats2half2_rn(vi[u].y, vf[u].y);
            h[3] = __floats2half2_rn(vo[u].y, vg[u].y);
            h[4] = __floats2half2_rn(vi[u].z, vf[u].z);
            h[5] = __floats2half2_rn(vo[u].z, vg[u].z);
            h[6] = __floats2half2_rn(vi[u].w, vf[u].w);
            h[7] = __floats2half2_rn(vo[u].w, vg[u].w);
            uint4* dst = (uint4*)&g_W[l][k][4 * j4];
            dst[0] = ((uint4*)h)[0];
            dst[1] = ((uint4*)h)[1];
        }
    } else if (b < PREP_WBLK + PREP_XBLK) {
        float4 v[8];
        #pragma unroll
        for (int it = 0; it < 8; ++it) {
            size_t i = (size_t)(b - PREP_WBLK) * 2048 + it * 256 + tid;
            v[it] = ((const float4*)x)[i];
        }
        #pragma unroll
        for (int it = 0; it < 8; ++it) {
            size_t i = (size_t)(b - PREP_WBLK) * 2048 + it * 256 + tid;
            size_t e = i * 4;
            size_t m = e >> 10, j = e & 1023;
            __half2 h[2];
            h[0] = __floats2half2_rn(v[it].x, v[it].y);
            h[1] = __floats2half2_rn(v[it].z, v[it].w);
            *(uint2*)&g_A[0][m][j] = *(uint2*)h;
        }
    } else {
        float4 v[8];
        #pragma unroll
        for (int it = 0; it < 8; ++it) {
            size_t i = (size_t)(b - PREP_WBLK - PREP_XBLK) * 2048 + it * 256 + tid;
            v[it] = ((const float4*)sh)[i];
        }
        #pragma unroll
        for (int it = 0; it < 8; ++it) {
            size_t i = (size_t)(b - PREP_WBLK - PREP_XBLK) * 2048 + it * 256 + tid;
            size_t e = i * 4;
            size_t l = e / ((size_t)B_ * H_);
            size_t r = e % ((size_t)B_ * H_);
            size_t m = r >> 10, j = r & 1023;
            __half2 h[2];
            h[0] = __floats2half2_rn(v[it].x, v[it].y);
            h[1] = __floats2half2_rn(v[it].z, v[it].w);
            *(uint2*)&g_A[l][m][H_ + j] = *(uint2*)h;
        }
    }
}

// ---------------- tile config ----------------
#define BK      32
#define ASTRIDE 80
#define BSTRIDE 272
#define A_STG   (128 * ASTRIDE)    // 10240
#define B_STG   (BK * BSTRIDE)     // 8704
#define STG     (A_STG + B_STG)    // 18944
#define NSTAGE  5
#define CIN_STRIDE 144
#define CIN_BYTES  (128 * CIN_STRIDE)
#define SMEM_G  (NSTAGE * STG + CIN_BYTES)     // 113152
#define NTILES  (DEPTH * 32 * 32)              // 4096
#define GRID_P  296
#define NIT     (K_ / BK)                      // 64

// ---------------- persistent fused GEMM + LSTM, mbarrier pipeline v2 ----------------
__global__ void __launch_bounds__(256, 2)
lstm_all(const float* __restrict__ bias_all, const float* __restrict__ sc_all,
         float* __restrict__ out_h, float* __restrict__ out_c,
         float* __restrict__ out_final) {
    extern __shared__ __align__(16) char smem[];
    __shared__ int s_t;
    __shared__ __align__(16) uint64_t s_mb[2 * NSTAGE];   // full[0..4], empty[0..4]
    const int tid = threadIdx.x;
    const int wid = tid >> 5, lane = tid & 31;
    const int wm = (wid >> 2) * 64, wn = (wid & 3) * 32;
    const uint32_t sbase = smem_u32(smem);
    const uint32_t scin  = sbase + NSTAGE * STG;
    const uint32_t mbF   = smem_u32(&s_mb[0]);
    const uint32_t mbE   = smem_u32(&s_mb[NSTAGE]);

    const int ar = tid >> 1, ac = (tid & 1) * 2;
    const int br = tid >> 4, bc = tid & 15;

    uint32_t aoff[4], boff[2];
    #pragma unroll
    for (int mf = 0; mf < 4; ++mf)
        aoff[mf] = (wm + mf * 16 + (lane & 15)) * ASTRIDE + (lane >> 4) * 16;
    #pragma unroll
    for (int ns = 0; ns < 2; ++ns)
        boff[ns] = (lane & 15) * BSTRIDE + (wn + ns * 16 + (lane >> 4) * 8) * 2;

    for (;;) {
        if (tid == 0) s_t = atomicAdd(&g_ticket, 1);
        __syncthreads();
        const int t = s_t;
        if (t >= NTILES) return;
        const int layer = t >> 10;
        const int mb = (t >> 5) & 31;
        const int nb = t & 31;
        const int m0 = mb * 128, n0 = nb * 128;
        const int jbase = n0 >> 2;

        const float* bias = bias_all + (size_t)layer * N4H;
        const float* c_in = sc_all + (size_t)layer * B_ * H_;
        float* h_out = out_h + (size_t)layer * B_ * H_;
        float* c_out = out_c + (size_t)layer * B_ * H_;
        float* final_out = (layer == DEPTH - 1) ? out_final : nullptr;
        const __half* Ag = &g_A[layer][0][0];
        const __half* Wg = &g_W[layer][0][0];
        __half* a_next = (layer + 1 < DEPTH) ? &g_A[layer + 1][0][0] : nullptr;

        // per-tile barrier re-init (all prior arrivals retired at tile end)
        if (tid == 0) {
            #pragma unroll
            for (int s = 0; s < NSTAGE; ++s) {
                MBAR_INIT(mbF + s * 8, 256);
                MBAR_INIT(mbE + s * 8, 256);
            }
            if (layer > 0) wait_ge(&g_ready[layer - 1][mb], 32);
        }
        __syncthreads();

        // c_in: the only committed cp.async group
        #pragma unroll
        for (int it = 0; it < 4; ++it) {
            int idx = tid + 256 * it;
            int r = idx >> 3, ch = idx & 7;
            cp16(scin + r * CIN_STRIDE + ch * 16,
                 c_in + (size_t)(m0 + r) * H_ + jbase + ch * 4);
        }
        asm volatile("cp.async.commit_group;" ::: "memory");

        auto load_stage = [&](int s, int k0) {
            uint32_t da = sbase + s * STG;
            uint32_t db = da + A_STG;
            cp16(da + ar * ASTRIDE + ac * 16,       Ag + (size_t)(m0 + ar) * K_ + k0 + ac * 8);
            cp16(da + ar * ASTRIDE + (ac + 1) * 16, Ag + (size_t)(m0 + ar) * K_ + k0 + (ac + 1) * 8);
            cp16(db + br * BSTRIDE + bc * 16,        Wg + (size_t)(k0 + br) * N4H + n0 + bc * 8);
            cp16(db + (br + 16) * BSTRIDE + bc * 16, Wg + (size_t)(k0 + br + 16) * N4H + n0 + bc * 8);
            CPASYNC_MBAR_ARRIVE(mbF + s * 8);
        };

        // prologue: fill all 5 stages
        #pragma unroll
        for (int s = 0; s < NSTAGE; ++s) load_stage(s, s * BK);

        float acc[4][4][4];
        #pragma unroll
        for (int i = 0; i < 4; ++i)
            #pragma unroll
            for (int j = 0; j < 4; ++j)
                #pragma unroll
                for (int q2 = 0; q2 < 4; ++q2) acc[i][j][q2] = 0.f;

        // mainloop: consume slot kt%5 @ parity (kt/5)&1.
        // Deferred reload: at iter kt, reload slot freed at use u=kt-2 (target chunk u+5),
        // waiting on empty arrivals that are 2 iterations old -> warps may slip.
        int ph = 0, ph2 = 0;
        #pragma unroll 1
        for (int kt = 0; kt < NIT; ++kt) {
            const int slot = kt % NSTAGE;
            const uint32_t da = sbase + slot * STG;
            const uint32_t db = da + A_STG;

            MBAR_WAIT(mbF + slot * 8, ph);

            uint32_t af[4][4], bf[2][4];
            #pragma unroll
            for (int mf = 0; mf < 4; ++mf) ldsm4(af[mf], da + aoff[mf]);
            #pragma unroll
            for (int ns = 0; ns < 2; ++ns) ldsm4t(bf[ns], db + boff[ns]);
            #pragma unroll
            for (int mf = 0; mf < 4; ++mf)
                #pragma unroll
                for (int nf = 0; nf < 4; ++nf)
                    mma16816(acc[mf][nf], af[mf], &bf[nf >> 1][(nf & 1) * 2]);
            #pragma unroll
            for (int mf = 0; mf < 4; ++mf) ldsm4(af[mf], da + aoff[mf] + 32);
            #pragma unroll
            for (int ns = 0; ns < 2; ++ns) ldsm4t(bf[ns], db + boff[ns] + 16 * BSTRIDE);
            MBAR_ARRIVE(mbE + slot * 8);     // done reading slot (use kt)
            #pragma unroll
            for (int mf = 0; mf < 4; ++mf)
                #pragma unroll
                for (int nf = 0; nf < 4; ++nf)
                    mma16816(acc[mf][nf], af[mf], &bf[nf >> 1][(nf & 1) * 2]);

            const int u = kt - 2;
            if (u >= 0) {
                if (u + NSTAGE < NIT) {
                    const int su = u % NSTAGE;
                    MBAR_WAIT(mbE + su * 8, ph2);     // all 256 done with use u
                    load_stage(su, (u + NSTAGE) * BK);
                }
                if ((u % NSTAGE) == NSTAGE - 1) ph2 ^= 1;
            }
            if (slot == NSTAGE - 1) ph ^= 1;
        }

        asm volatile("cp.async.wait_group 0;" ::: "memory");   // c_in group
        __syncthreads();   // all ldsm of slots 3/4 done before staging reuse

        // ---- LSTM epilogue (staging in slot-3/4 region; mapping verified) ----
        float* sh_h = (float*)(smem + 3 * STG);          // [128][33]
        float* sh_c = sh_h + 128 * 33;                   // [128][33]
        const float* sh_cin = (const float*)(smem + NSTAGE * STG);

        const int q = lane & 3;
        const bool has_if = (q & 1) == 0;
        const int rloc = wm + (lane >> 2);

        float bi[4], bfs[4], bo[4], bg[4];
        int jloc[4];
        #pragma unroll
        for (int nf = 0; nf < 4; ++nf) {
            int jl = (wn >> 2) + nf * 2 + (q >> 1);
            jloc[nf] = jl;
            int j = jbase + jl;
            bi[nf]  = bias[j];
            bfs[nf] = bias[1024 + j];
            bo[nf]  = bias[2048 + j];
            bg[nf]  = bias[3072 + j];
        }

        #pragma unroll
        for (int mf = 0; mf < 4; ++mf) {
            #pragma unroll
            for (int nf = 0; nf < 4; ++nf) {
                float v0 = acc[mf][nf][0], v1 = acc[mf][nf][1];
                float v2 = acc[mf][nf][2], v3 = acc[mf][nf][3];
                float p0 = __shfl_xor_sync(0xffffffffu, v0, 1);
                float p1 = __shfl_xor_sync(0xffffffffu, v1, 1);
                float p2 = __shfl_xor_sync(0xffffffffu, v2, 1);
                float p3 = __shfl_xor_sync(0xffffffffu, v3, 1);
                float zi, zf, zo, zg;
                int ml;
                if (has_if) { zi = v0; zf = v1; zo = p0; zg = p1; ml = rloc + mf * 16; }
                else        { zi = p2; zf = p3; zo = v2; zg = v3; ml = rloc + mf * 16 + 8; }
                const int jl = jloc[nf];
                float ig = sigm(zi + bi[nf]);
                float fg = sigm(zf + bfs[nf]);
                float og = sigm(zo + bo[nf]);
                float gg = tanhf(zg + bg[nf]);
                float cn = sh_cin[ml * 36 + jl] * fg + gg * ig;
                float hn = tanhf(cn) * og;
                sh_h[ml * 33 + jl] = hn;
                sh_c[ml * 33 + jl] = cn;
            }
        }
        __syncthreads();

        // ---- vectorized output pass ----
        #pragma unroll
        for (int it = 0; it < 4; ++it) {
            int idx = tid + 256 * it;            // 0..1023
            int r = idx >> 3, c4 = (idx & 7) * 4;
            float4 hv = make_float4(sh_h[r * 33 + c4],     sh_h[r * 33 + c4 + 1],
                                    sh_h[r * 33 + c4 + 2], sh_h[r * 33 + c4 + 3]);
            float4 cv = make_float4(sh_c[r * 33 + c4],     sh_c[r * 33 + c4 + 1],
                                    sh_c[r * 33 + c4 + 2], sh_c[r * 33 + c4 + 3]);
            const size_t off = (size_t)(m0 + r) * H_ + jbase + c4;
            stcs4(&h_out[off], hv);
            stcs4(&c_out[off], cv);
            if (final_out) stcs4(&final_out[off], hv);
            if (a_next) {
                __half2 pk[2];
                pk[0] = __floats2half2_rn(hv.x, hv.y);
                pk[1] = __floats2half2_rn(hv.z, hv.w);
                *(uint2*)&a_next[(size_t)(m0 + r) * K_ + jbase + c4] = *(uint2*)pk;
            }
        }
        __syncthreads();
        if (tid == 0)
            asm volatile("red.release.gpu.global.add.s32 [%0], 1;"
                         :: "l"(__cvta_generic_to_global(&g_ready[layer][mb])) : "memory");
    }
}

// ---------------- launch ----------------
extern "C" void kernel_launch(void* const* d_in, const int* in_sizes, int n_in,
                              void* d_out, int out_size) {
    const float* x  = (const float*)d_in[0];
    const float* sh = (const float*)d_in[1];
    const float* sc = (const float*)d_in[2];
    const float* W  = (const float*)d_in[3];
    const float* b  = (const float*)d_in[4];
    float* out = (float*)d_out;

    const size_t BH = (size_t)B_ * H_;
    float* out_final = out;
    float* out_h     = out + BH;
    float* out_c     = out + BH + DEPTH * BH;

    cudaFuncSetAttribute(lstm_all, cudaFuncAttributeMaxDynamicSharedMemorySize, SMEM_G);

    prep<<<PREP_GRID, 256>>>(W, x, sh);
    lstm_all<<<GRID_P, 256, SMEM_G>>>(b, sc, out_h, out_c, out_final);
}